// round 7
// baseline (speedup 1.0000x reference)
#include <cuda_runtime.h>
#include <cuda_fp16.h>
#include <math_constants.h>
#include <cstdint>

#define Bq 4
#define Tq 1024
#define Cq 16
#define Dq 256
#define NHEADS (Bq*Cq)
#define MTOT (Bq*Tq*Cq)

__device__ __align__(128) __half g_xb[(size_t)MTOT * Dq];
__device__ __align__(128) __half g_wb[3 * Dq * Dq];
__device__ __align__(128) __half g_q [(size_t)NHEADS * Tq * Dq];
__device__ __align__(128) __half g_k [(size_t)NHEADS * Tq * Dq];
__device__ __align__(128) __half g_v [(size_t)NHEADS * Tq * Dq];
__device__ __align__(128) unsigned char g_mt[NHEADS * Tq];

static __device__ __forceinline__ unsigned packh(float a, float b) {
    __half2 h = __floats2half2_rn(a, b);
    return *reinterpret_cast<unsigned*>(&h);
}
static __device__ __forceinline__ float2 unph(unsigned u) {
    __half2 h = *reinterpret_cast<__half2*>(&u);
    return __half22float2(h);
}
static __device__ __forceinline__ unsigned hadd2u(unsigned a, unsigned b) {
    __half2 r = __hadd2(*reinterpret_cast<__half2*>(&a),
                        *reinterpret_cast<__half2*>(&b));
    return *reinterpret_cast<unsigned*>(&r);
}
static __device__ __forceinline__ void mma_f16_f16(
    unsigned& d0, unsigned& d1,
    unsigned a0, unsigned a1, unsigned a2, unsigned a3,
    unsigned b0, unsigned b1)
{
    asm volatile(
        "mma.sync.aligned.m16n8k16.row.col.f16.f16.f16.f16 "
        "{%0,%1}, {%2,%3,%4,%5}, {%6,%7}, {%0,%1};\n"
        : "+r"(d0), "+r"(d1)
        : "r"(a0), "r"(a1), "r"(a2), "r"(a3), "r"(b0), "r"(b1));
}
static __device__ __forceinline__ void ldsm_x4(
    unsigned& r0, unsigned& r1, unsigned& r2, unsigned& r3, unsigned addr)
{
    asm volatile("ldmatrix.sync.aligned.m8n8.x4.shared.b16 {%0,%1,%2,%3}, [%4];"
        : "=r"(r0), "=r"(r1), "=r"(r2), "=r"(r3) : "r"(addr));
}
static __device__ __forceinline__ void ldsm_x4_t(
    unsigned& r0, unsigned& r1, unsigned& r2, unsigned& r3, unsigned addr)
{
    asm volatile("ldmatrix.sync.aligned.m8n8.x4.trans.shared.b16 {%0,%1,%2,%3}, [%4];"
        : "=r"(r0), "=r"(r1), "=r"(r2), "=r"(r3) : "r"(addr));
}

#define CPA16(d, s) asm volatile("cp.async.cg.shared.global [%0], [%1], 16;" :: "r"(d), "l"(s))
#define CP_COMMIT() asm volatile("cp.async.commit_group;")
#define CP_WAIT(n)  asm volatile("cp.async.wait_group %0;" :: "n"(n))

// ---------------------------------------------------------------------------
__global__ void conv_x_kernel(const float* __restrict__ x)
{
    int i = blockIdx.x * blockDim.x + threadIdx.x;
    const float4 v = ((const float4*)x)[i];
    ((uint2*)g_xb)[i] = make_uint2(packh(v.x, v.y), packh(v.z, v.w));
}
__global__ void conv_w_kernel(const float* __restrict__ wq,
                              const float* __restrict__ wk,
                              const float* __restrict__ wv)
{
    int i = blockIdx.x * blockDim.x + threadIdx.x;
    g_wb[i]          = __float2half(wq[i]);
    g_wb[i + 65536]  = __float2half(wk[i]);
    g_wb[i + 131072] = __float2half(wv[i]);
}
__global__ void conv_m_kernel(const unsigned char* __restrict__ xmask)
{
    int i = blockIdx.x * blockDim.x + threadIdx.x;
    int h = i >> 10, t = i & 1023;
    int b = h >> 4,  c = h & 15;
    g_mt[i] = xmask[(size_t)((b << 10) + t) * Cq + c];
}

// ---------------------------------------------------------------------------
// QKV projection (unchanged from R6): mma.sync f16/f16acc, CTA 128Mx256N.
// ---------------------------------------------------------------------------
#define QX_OFF 0u
#define QW0_OFF 67584u
#define QW1_OFF 137216u
#define QK_SMEM (137216 + 69632)

__global__ __launch_bounds__(256, 1) void qkv_mma_kernel(
    const int*   __restrict__ pos,
    const float* __restrict__ pe,
    const float* __restrict__ bq,
    const float* __restrict__ bk,
    const float* __restrict__ bv)
{
    extern __shared__ char sm[];
    const unsigned su = (unsigned)__cvta_generic_to_shared(sm);
    const int tid = threadIdx.x, w = tid >> 5, lane = tid & 31;
    const int q = lane & 3, lr = lane >> 2, g = lane >> 3, r8 = lane & 7;
    const int wm = w >> 2, wn = w & 3;
    const int mat = blockIdx.x;
    const int m0  = blockIdx.y * 128;

    const __half* xb = g_xb + (size_t)m0 * Dq;
#pragma unroll
    for (int it = 0; it < 16; ++it) {
        int idx = it * 256 + tid;
        int row = idx >> 5, ch = idx & 31;
        CPA16(su + QX_OFF + (unsigned)(row * 528 + ch * 16), xb + row * Dq + ch * 8);
    }
    const __half* wb = g_wb + mat * 65536;
#pragma unroll
    for (int it = 0; it < 16; ++it) {
        int idx = it * 256 + tid;
        int row = idx >> 4, ch = idx & 15;
        CPA16(su + QW0_OFF + (unsigned)(row * 272 + ch * 16), wb + row * Dq + ch * 8);
    }
    CP_COMMIT();
#pragma unroll
    for (int it = 0; it < 16; ++it) {
        int idx = it * 256 + tid;
        int row = idx >> 4, ch = idx & 15;
        CPA16(su + QW1_OFF + (unsigned)(row * 272 + ch * 16), wb + row * Dq + 128 + ch * 8);
    }
    CP_COMMIT();

    unsigned acc[4][8][2];
#pragma unroll
    for (int mt = 0; mt < 4; ++mt)
#pragma unroll
        for (int nt = 0; nt < 8; ++nt) { acc[mt][nt][0] = 0u; acc[mt][nt][1] = 0u; }

    const unsigned a_base = su + QX_OFF +
        (unsigned)((wm * 64 + (g & 1) * 8 + r8) * 528 + ((g >> 1) * 8) * 2);
    const unsigned b_base = su + QW0_OFF +
        (unsigned)((wn * 64 + (g >> 1) * 8 + r8) * 272 + ((g & 1) * 8) * 2);

#pragma unroll
    for (int ph = 0; ph < 2; ++ph) {
        if (ph == 0) { CP_WAIT(1); } else { CP_WAIT(0); }
        __syncthreads();
        const unsigned ab = a_base + (unsigned)ph * 256u;
        const unsigned bb = b_base + (unsigned)ph * (QW1_OFF - QW0_OFF);
#pragma unroll
        for (int kk = 0; kk < 8; ++kk) {
            unsigned af[4][4];
#pragma unroll
            for (int mt = 0; mt < 4; ++mt)
                ldsm_x4(af[mt][0], af[mt][1], af[mt][2], af[mt][3],
                        ab + (unsigned)(mt * 16 * 528) + kk * 32);
#pragma unroll
            for (int nt = 0; nt < 4; ++nt) {
                unsigned b0, b1, b2, b3;
                ldsm_x4(b0, b1, b2, b3, bb + (unsigned)(nt * 16 * 272) + kk * 32);
#pragma unroll
                for (int mt = 0; mt < 4; ++mt) {
                    mma_f16_f16(acc[mt][2*nt][0],   acc[mt][2*nt][1],
                                af[mt][0], af[mt][1], af[mt][2], af[mt][3], b0, b1);
                    mma_f16_f16(acc[mt][2*nt+1][0], acc[mt][2*nt+1][1],
                                af[mt][0], af[mt][1], af[mt][2], af[mt][3], b2, b3);
                }
            }
        }
    }

    const float* bias = (mat == 0) ? bq : (mat == 1) ? bk : bv;
    __half* outp = (mat == 0) ? g_q : (mat == 1) ? g_k : g_v;

#pragma unroll
    for (int mt = 0; mt < 4; ++mt) {
        const int tokA = m0 + wm * 64 + mt * 16 + lr;
        const int tokB = tokA + 8;
        const int bA = tokA >> 14, tA = (tokA >> 4) & (Tq-1), cA = tokA & (Cq-1);
        const int bB = tokB >> 14, tB = (tokB >> 4) & (Tq-1), cB = tokB & (Cq-1);
        __half* rowA = outp + ((size_t)(bA * Cq + cA) * Tq + tA) * Dq;
        __half* rowB = outp + ((size_t)(bB * Cq + cB) * Tq + tB) * Dq;
        int pA = 0, pB = 0;
        if (mat < 2) { pA = pos[tokA]; pB = pos[tokB]; }
#pragma unroll
        for (int nt = 0; nt < 8; ++nt) {
            const int col = wn * 64 + nt * 8 + 2 * q;
            const float2 b2 = *(const float2*)(bias + col);
            float2 va = unph(acc[mt][nt][0]);
            float2 vb = unph(acc[mt][nt][1]);
            float v0 = va.x + b2.x, v1 = va.y + b2.y;
            float v2 = vb.x + b2.x, v3 = vb.y + b2.y;
            if (mat < 2) {
                const float2 csA = *(const float2*)(pe + (size_t)pA * Dq + col);
                const float2 csB = *(const float2*)(pe + (size_t)pB * Dq + col);
                float r0 = v0 * csA.x - v1 * csA.y;
                v1 = v0 * csA.y + v1 * csA.x; v0 = r0;
                float r2 = v2 * csB.x - v3 * csB.y;
                v3 = v2 * csB.y + v3 * csB.x; v2 = r2;
            }
            *(unsigned*)&rowA[col] = packh(v0, v1);
            *(unsigned*)&rowB[col] = packh(v2, v3);
        }
    }
}

// ---------------------------------------------------------------------------
// Flash attention, d-split warp pairs + frozen-max softmax.
// CTA = (head, 128 q-rows). 8 warps: rg = w>>1 (rows rg*32..+31), dh = w&1
// (d-cols dh*128..+127). Partial S exchanged between pair via smem.
// ---------------------------------------------------------------------------
#define STR 264
#define KBYTES (64 * STR * 2)          // 33792
#define STAGEB (2 * KBYTES)            // 67584
#define EXCH_OFF  (2 * STAGEB)         // 135168, 32KB
#define STATS_OFF (EXCH_OFF + 32768)   // 167936, 2KB
#define QM_OFF    (STATS_OFF + 2048)   // 169984, 128B
#define KM_OFF    (QM_OFF + 128)       // 170112, 128B
#define ATTN_SMEM (KM_OFF + 128 + 128)

__global__ __launch_bounds__(256, 1) void attn_ds_kernel(
    const float* __restrict__ x,
    const float* __restrict__ lng,
    const float* __restrict__ lnb,
    const float* __restrict__ lsg,
    float* __restrict__ out)
{
    extern __shared__ char smraw[];
    unsigned* exch = (unsigned*)(smraw + EXCH_OFF);
    float2*   stats = (float2*)(smraw + STATS_OFF);
    unsigned char* sQm = (unsigned char*)(smraw + QM_OFF);
    unsigned char* sKmBase = (unsigned char*)(smraw + KM_OFF);
    const unsigned smem_u = (unsigned)__cvta_generic_to_shared(smraw);
    const unsigned sqm_u  = smem_u + QM_OFF;
    const unsigned skm_u  = smem_u + KM_OFF;

    const int tid  = threadIdx.x;
    const int w    = tid >> 5;
    const int lane = tid & 31;
    const int q    = lane & 3;
    const int lr   = lane >> 2;
    const int g    = lane >> 3;
    const int r8   = lane & 7;
    const int rg   = w >> 1;       // row group (32 rows)
    const int dh   = w & 1;        // d half

    const int h  = blockIdx.y;
    const int b  = h >> 4, c = h & 15;
    const int q0 = blockIdx.x * 128;

    const __half* qg = g_q + ((size_t)h * Tq + q0) * Dq;
    const __half* kg = g_k + (size_t)h * Tq * Dq;
    const __half* vg = g_v + (size_t)h * Tq * Dq;
    const unsigned char* mg = g_mt + h * Tq;

    // ---- stage Q into stage-1 region, read fragments, release ----
    const unsigned qs = smem_u + STAGEB;
#pragma unroll
    for (int it = 0; it < 16; ++it) {
        int idx = it * 256 + tid;
        int row = idx >> 5, cc = idx & 31;
        CPA16(qs + (unsigned)(row * STR * 2 + cc * 16), qg + row * Dq + cc * 8);
    }
    if (tid < 8) CPA16(sqm_u + tid * 16, mg + q0 + tid * 16);
    CP_COMMIT();
    CP_WAIT(0);
    __syncthreads();

    unsigned qf[8][2][4];   // [kk within d-half][mt][frag]
#pragma unroll
    for (int mt = 0; mt < 2; ++mt) {
        const unsigned qa = qs +
            (unsigned)((rg * 32 + mt * 16 + (g & 1) * 8 + r8) * STR + (g >> 1) * 8) * 2;
#pragma unroll
        for (int kk = 0; kk < 8; ++kk)
            ldsm_x4(qf[kk][mt][0], qf[kk][mt][1], qf[kk][mt][2], qf[kk][mt][3],
                    qa + (unsigned)(dh * 256 + kk * 32));
    }
    int qm[2][2];
#pragma unroll
    for (int mt = 0; mt < 2; ++mt) {
        qm[mt][0] = sQm[rg * 32 + mt * 16 + lr];
        qm[mt][1] = sQm[rg * 32 + mt * 16 + lr + 8];
    }
    __syncthreads();

    auto issue = [&](int kt) {
        const int stage = kt & 1;
        const unsigned sb = smem_u + stage * STAGEB;
        const int k0 = kt * 64;
#pragma unroll
        for (int it = 0; it < 8; ++it) {
            int idx = it * 256 + tid;
            int row = idx >> 5, cc = idx & 31;
            CPA16(sb + (unsigned)(row * STR * 2 + cc * 16),
                  kg + (size_t)(k0 + row) * Dq + cc * 8);
            CPA16(sb + KBYTES + (unsigned)(row * STR * 2 + cc * 16),
                  vg + (size_t)(k0 + row) * Dq + cc * 8);
        }
        if (tid < 4) CPA16(skm_u + stage * 64 + tid * 16, mg + k0 + tid * 16);
    };
    issue(0); CP_COMMIT();
    issue(1); CP_COMMIT();

    const unsigned koff = ((unsigned)((g >> 1) * 8 + r8) * STR + (g & 1) * 8) * 2;
    const unsigned voff = ((unsigned)((g & 1) * 8 + r8) * STR + (g >> 1) * 8) * 2;

    unsigned oacc[2][16][2];
#pragma unroll
    for (int mt = 0; mt < 2; ++mt)
#pragma unroll
        for (int j = 0; j < 16; ++j) { oacc[mt][j][0] = 0u; oacc[mt][j][1] = 0u; }
    float lsum[2][2] = {{0.f, 0.f}, {0.f, 0.f}};
    float mU[2][2]   = {{0.f, 0.f}, {0.f, 0.f}};

    const int exw  = w * 1024;          // own exchange slot (u32 index)
    const int exp_ = (w ^ 1) * 1024;    // partner slot

    for (int kt = 0; kt < 16; ++kt) {
        CP_WAIT(1);
        __syncthreads();
        const int stage = kt & 1;
        const unsigned kb_s = smem_u + stage * STAGEB;
        const unsigned vb_s = kb_s + KBYTES;
        const unsigned char* km = sKmBase + stage * 64;

        // ---- partial S over this warp's d-half ----
        unsigned sacc[2][8][2];
#pragma unroll
        for (int mt = 0; mt < 2; ++mt)
#pragma unroll
            for (int nf = 0; nf < 8; ++nf) { sacc[mt][nf][0] = 0u; sacc[mt][nf][1] = 0u; }
#pragma unroll
        for (int kk = 0; kk < 8; ++kk) {
#pragma unroll
            for (int ng = 0; ng < 4; ++ng) {
                unsigned b0, b1, b2, b3;
                ldsm_x4(b0, b1, b2, b3,
                        kb_s + (unsigned)(ng * 16 * STR * 2 + dh * 256 + kk * 32) + koff);
#pragma unroll
                for (int mt = 0; mt < 2; ++mt) {
                    mma_f16_f16(sacc[mt][2*ng][0],   sacc[mt][2*ng][1],
                        qf[kk][mt][0], qf[kk][mt][1], qf[kk][mt][2], qf[kk][mt][3], b0, b1);
                    mma_f16_f16(sacc[mt][2*ng+1][0], sacc[mt][2*ng+1][1],
                        qf[kk][mt][0], qf[kk][mt][1], qf[kk][mt][2], qf[kk][mt][3], b2, b3);
                }
            }
        }

        // ---- exchange partial S with pair partner, combine ----
#pragma unroll
        for (int mt = 0; mt < 2; ++mt)
#pragma unroll
            for (int nf = 0; nf < 8; ++nf) {
                exch[exw + (mt * 8 + nf) * 64 + lane]      = sacc[mt][nf][0];
                exch[exw + (mt * 8 + nf) * 64 + 32 + lane] = sacc[mt][nf][1];
            }
        __syncthreads();
#pragma unroll
        for (int mt = 0; mt < 2; ++mt)
#pragma unroll
            for (int nf = 0; nf < 8; ++nf) {
                sacc[mt][nf][0] = hadd2u(sacc[mt][nf][0],
                                         exch[exp_ + (mt * 8 + nf) * 64 + lane]);
                sacc[mt][nf][1] = hadd2u(sacc[mt][nf][1],
                                         exch[exp_ + (mt * 8 + nf) * 64 + 32 + lane]);
            }

        // ---- frozen max: establish at kt 0 from combined, masked S ----
        if (kt == 0) {
            float tmax[2][2] = {{-CUDART_INF_F, -CUDART_INF_F},
                                {-CUDART_INF_F, -CUDART_INF_F}};
#pragma unroll
            for (int mt = 0; mt < 2; ++mt)
#pragma unroll
                for (int nf = 0; nf < 8; ++nf) {
                    const int cc = nf * 8 + 2 * q;
                    const int k0m = km[cc], k1m = km[cc + 1];
                    float2 lo = unph(sacc[mt][nf][0]);
                    float2 hi = unph(sacc[mt][nf][1]);
                    float s0 = (qm[mt][0] | k0m) ? -CUDART_INF_F : lo.x * 0.0625f;
                    float s1 = (qm[mt][0] | k1m) ? -CUDART_INF_F : lo.y * 0.0625f;
                    float s2 = (qm[mt][1] | k0m) ? -CUDART_INF_F : hi.x * 0.0625f;
                    float s3 = (qm[mt][1] | k1m) ? -CUDART_INF_F : hi.y * 0.0625f;
                    tmax[mt][0] = fmaxf(tmax[mt][0], fmaxf(s0, s1));
                    tmax[mt][1] = fmaxf(tmax[mt][1], fmaxf(s2, s3));
                }
#pragma unroll
            for (int mt = 0; mt < 2; ++mt)
#pragma unroll
                for (int ab = 0; ab < 2; ++ab) {
                    float t = tmax[mt][ab];
                    t = fmaxf(t, __shfl_xor_sync(0xffffffffu, t, 1));
                    t = fmaxf(t, __shfl_xor_sync(0xffffffffu, t, 2));
                    mU[mt][ab] = (t < -1e30f) ? 0.f : t;
                }
        }

        // ---- p = exp(s*scale - mU), masked entries exactly 0 ----
        unsigned pa[2][4][4];
#pragma unroll
        for (int mt = 0; mt < 2; ++mt)
#pragma unroll
            for (int kkv = 0; kkv < 4; ++kkv) {
                const int nfA = 2 * kkv, nfB = 2 * kkv + 1;
                const int c0 = nfA * 8 + 2 * q, c1 = nfB * 8 + 2 * q;
                const int ka0 = km[c0], ka1 = km[c0 + 1];
                const int kb0 = km[c1], kb1 = km[c1 + 1];
                float2 lA = unph(sacc[mt][nfA][0]);
                float2 hA = unph(sacc[mt][nfA][1]);
                float2 lB = unph(sacc[mt][nfB][0]);
                float2 hB = unph(sacc[mt][nfB][1]);
                float p00 = (qm[mt][0] | ka0) ? 0.f : __expf(lA.x * 0.0625f - mU[mt][0]);
                float p01 = (qm[mt][0] | ka1) ? 0.f : __expf(lA.y * 0.0625f - mU[mt][0]);
                float p02 = (qm[mt][1] | ka0) ? 0.f : __expf(hA.x * 0.0625f - mU[mt][1]);
                float p03 = (qm[mt][1] | ka1) ? 0.f : __expf(hA.y * 0.0625f - mU[mt][1]);
                float p10 = (qm[mt][0] | kb0) ? 0.f : __expf(lB.x * 0.0625f - mU[mt][0]);
                float p11 = (qm[mt][0] | kb1) ? 0.f : __expf(lB.y * 0.0625f - mU[mt][0]);
                float p12 = (qm[mt][1] | kb0) ? 0.f : __expf(hB.x * 0.0625f - mU[mt][1]);
                float p13 = (qm[mt][1] | kb1) ? 0.f : __expf(hB.y * 0.0625f - mU[mt][1]);
                lsum[mt][0] += p00 + p01 + p10 + p11;
                lsum[mt][1] += p02 + p03 + p12 + p13;
                pa[mt][kkv][0] = packh(p00, p01);
                pa[mt][kkv][1] = packh(p02, p03);
                pa[mt][kkv][2] = packh(p10, p11);
                pa[mt][kkv][3] = packh(p12, p13);
            }

        // ---- O += P V over this warp's d-half ----
#pragma unroll
        for (int kkv = 0; kkv < 4; ++kkv) {
#pragma unroll
            for (int dgr = 0; dgr < 8; ++dgr) {
                unsigned v0, v1, v2, v3;
                ldsm_x4_t(v0, v1, v2, v3,
                          vb_s + (unsigned)(kkv * 16 * STR * 2 + dh * 256 + dgr * 32) + voff);
#pragma unroll
                for (int mt = 0; mt < 2; ++mt) {
                    mma_f16_f16(oacc[mt][2*dgr][0],   oacc[mt][2*dgr][1],
                        pa[mt][kkv][0], pa[mt][kkv][1], pa[mt][kkv][2], pa[mt][kkv][3], v0, v1);
                    mma_f16_f16(oacc[mt][2*dgr+1][0], oacc[mt][2*dgr+1][1],
                        pa[mt][kkv][0], pa[mt][kkv][1], pa[mt][kkv][2], pa[mt][kkv][3], v2, v3);
                }
            }
        }
        __syncthreads();
        if (kt + 2 < 16) issue(kt + 2);
        CP_COMMIT();
    }

    // ---- epilogue ----
    float inv[2][2];
#pragma unroll
    for (int mt = 0; mt < 2; ++mt)
#pragma unroll
        for (int ab = 0; ab < 2; ++ab) {
            float l = lsum[mt][ab];
            l += __shfl_xor_sync(0xffffffffu, l, 1);
            l += __shfl_xor_sync(0xffffffffu, l, 2);
            inv[mt][ab] = (l > 0.f) ? (1.f / l) : 0.f;
        }

    // pass 1: partial LN stats over this warp's d-half
    float psum[2][2] = {{0.f,0.f},{0.f,0.f}}, pssq[2][2] = {{0.f,0.f},{0.f,0.f}};
#pragma unroll
    for (int mt = 0; mt < 2; ++mt) {
        const int rowA = rg * 32 + mt * 16 + lr;
        const size_t miA = (size_t)(b * Tq + q0 + rowA) * Cq + c;
        const size_t miB = (size_t)(b * Tq + q0 + rowA + 8) * Cq + c;
        const float* xA = x + miA * Dq;
        const float* xB = x + miB * Dq;
#pragma unroll
        for (int dg = 0; dg < 16; ++dg) {
            const int cc = dh * 128 + dg * 8 + 2 * q;
            const float2 g2 = *(const float2*)(lsg + cc);
            const float2 xa = *(const float2*)(xA + cc);
            const float2 xb2 = *(const float2*)(xB + cc);
            const float2 oa = unph(oacc[mt][dg][0]);
            const float2 ob = unph(oacc[mt][dg][1]);
            float y0 = xa.x  + g2.x * (oa.x * inv[mt][0]);
            float y1 = xa.y  + g2.y * (oa.y * inv[mt][0]);
            float y2 = xb2.x + g2.x * (ob.x * inv[mt][1]);
            float y3 = xb2.y + g2.y * (ob.y * inv[mt][1]);
            psum[mt][0] += y0 + y1;  pssq[mt][0] += y0 * y0 + y1 * y1;
            psum[mt][1] += y2 + y3;  pssq[mt][1] += y2 * y2 + y3 * y3;
        }
    }
#pragma unroll
    for (int mt = 0; mt < 2; ++mt)
#pragma unroll
        for (int ab = 0; ab < 2; ++ab) {
            psum[mt][ab] += __shfl_xor_sync(0xffffffffu, psum[mt][ab], 1);
            psum[mt][ab] += __shfl_xor_sync(0xffffffffu, psum[mt][ab], 2);
            pssq[mt][ab] += __shfl_xor_sync(0xffffffffu, pssq[mt][ab], 1);
            pssq[mt][ab] += __shfl_xor_sync(0xffffffffu, pssq[mt][ab], 2);
            if (q == 0) {
                const int row = rg * 32 + mt * 16 + lr + ab * 8;
                stats[row * 2 + dh] = make_float2(psum[mt][ab], pssq[mt][ab]);
            }
        }
    __syncthreads();

    // pass 2: full stats, recompute y, normalize, store
#pragma unroll
    for (int mt = 0; mt < 2; ++mt) {
        const int rowA = rg * 32 + mt * 16 + lr;
        float mu[2], rs[2];
#pragma unroll
        for (int ab = 0; ab < 2; ++ab) {
            const int row = rowA + ab * 8;
            const float2 s0 = stats[row * 2 + 0];
            const float2 s1 = stats[row * 2 + 1];
            const float m = (s0.x + s1.x) * (1.f / 256.f);
            mu[ab] = m;
            rs[ab] = rsqrtf((s0.y + s1.y) * (1.f / 256.f) - m * m + 1e-5f);
        }
        const size_t miA = (size_t)(b * Tq + q0 + rowA) * Cq + c;
        const size_t miB = (size_t)(b * Tq + q0 + rowA + 8) * Cq + c;
        const float* xA = x + miA * Dq;
        const float* xB = x + miB * Dq;
        float* oA = out + miA * Dq;
        float* oB = out + miB * Dq;
#pragma unroll
        for (int dg = 0; dg < 16; ++dg) {
            const int cc = dh * 128 + dg * 8 + 2 * q;
            const float2 g2 = *(const float2*)(lsg + cc);
            const float2 gg = *(const float2*)(lng + cc);
            const float2 bb = *(const float2*)(lnb + cc);
            const float2 xa = *(const float2*)(xA + cc);
            const float2 xb2 = *(const float2*)(xB + cc);
            const float2 oa = unph(oacc[mt][dg][0]);
            const float2 ob = unph(oacc[mt][dg][1]);
            float y0 = xa.x  + g2.x * (oa.x * inv[mt][0]);
            float y1 = xa.y  + g2.y * (oa.y * inv[mt][0]);
            float y2 = xb2.x + g2.x * (ob.x * inv[mt][1]);
            float y3 = xb2.y + g2.y * (ob.y * inv[mt][1]);
            float2 r0, r1;
            r0.x = (y0 - mu[0]) * rs[0] * gg.x + bb.x;
            r0.y = (y1 - mu[0]) * rs[0] * gg.y + bb.y;
            r1.x = (y2 - mu[1]) * rs[1] * gg.x + bb.x;
            r1.y = (y3 - mu[1]) * rs[1] * gg.y + bb.y;
            *(float2*)(oA + cc) = r0;
            *(float2*)(oB + cc) = r1;
        }
    }
}

// ---------------------------------------------------------------------------
extern "C" void kernel_launch(void* const* d_in, const int* in_sizes, int n_in,
                              void* d_out, int out_size)
{
    const float* x   = (const float*)d_in[0];
    const unsigned char* xmask = (const unsigned char*)d_in[1];
    const int*   pos = (const int*)d_in[2];
    const float* pe  = (const float*)d_in[3];
    const float* wq  = (const float*)d_in[4];
    const float* bq  = (const float*)d_in[5];
    const float* wk  = (const float*)d_in[6];
    const float* bk  = (const float*)d_in[7];
    const float* wv  = (const float*)d_in[8];
    const float* bv  = (const float*)d_in[9];
    const float* lng = (const float*)d_in[10];
    const float* lnb = (const float*)d_in[11];
    const float* lsg = (const float*)d_in[12];
    float* out = (float*)d_out;

    conv_x_kernel<<<(MTOT * Dq / 4) / 256, 256>>>(x);
    conv_w_kernel<<<(Dq * Dq) / 256, 256>>>(wq, wk, wv);
    conv_m_kernel<<<(NHEADS * Tq) / 256, 256>>>(xmask);

    cudaFuncSetAttribute(qkv_mma_kernel,
                         cudaFuncAttributeMaxDynamicSharedMemorySize, QK_SMEM);
    qkv_mma_kernel<<<dim3(3, MTOT / 128), 256, QK_SMEM>>>(pos, pe, bq, bk, bv);

    cudaFuncSetAttribute(attn_ds_kernel,
                         cudaFuncAttributeMaxDynamicSharedMemorySize, ATTN_SMEM);
    attn_ds_kernel<<<dim3(Tq / 128, NHEADS), 256, ATTN_SMEM>>>(
        x, lng, lnb, lsg, out);
}